// round 2
// baseline (speedup 1.0000x reference)
#include <cuda_runtime.h>
#include <math.h>
#include <stdint.h>

#define R_N 1000
#define K_N 80
#define NCLS_P1 81
#define IMG_W_F 1333.0f
#define IMG_H_F 800.0f
#define CPC 100      // candidates kept per class
#define TOPK_N 100
#define OUT_COLS 87

__device__ float g_thres;
__device__ unsigned int g_ord[K_N * CPC];   // orderable score keys, 0 = pad
__device__ int g_prop[K_N * CPC];           // original proposal row

__device__ __forceinline__ unsigned int ord32(float f) {
    unsigned int u = __float_as_uint(f);
    return (u & 0x80000000u) ? ~u : (u | 0x80000000u);
}

__device__ __forceinline__ unsigned long long umax64(unsigned long long a, unsigned long long b) {
    return a > b ? a : b;
}

// ---------------------------------------------------------------------------
// Kernel 1: threshold = min(0.05, (mean(fg) + max(fg)) / 2)
// ---------------------------------------------------------------------------
__global__ void __launch_bounds__(1024) thres_kernel(const float* __restrict__ scores) {
    __shared__ float s_sum[1024];
    __shared__ float s_max[1024];
    int t = threadIdx.x;
    float sum = 0.f, mx = -INFINITY;
    for (int idx = t; idx < R_N * K_N; idx += 1024) {
        int r = idx / K_N;
        int c = idx - r * K_N;
        float v = scores[r * NCLS_P1 + c];
        sum += v;
        mx = fmaxf(mx, v);
    }
    s_sum[t] = sum; s_max[t] = mx;
    __syncthreads();
    for (int s = 512; s > 0; s >>= 1) {
        if (t < s) {
            s_sum[t] += s_sum[t + s];
            s_max[t] = fmaxf(s_max[t], s_max[t + s]);
        }
        __syncthreads();
    }
    if (t == 0) {
        float mean = s_sum[0] / (float)(R_N * K_N);
        g_thres = fminf(0.05f, 0.5f * (mean + s_max[0]));
    }
}

// ---------------------------------------------------------------------------
// Kernel 2: per-class compact -> sort -> greedy NMS -> emit top-100 kept
// ---------------------------------------------------------------------------
__global__ void __launch_bounds__(1024) nms_kernel(const float* __restrict__ boxes,
                                                   const float* __restrict__ scores) {
    __shared__ float  s_score[1024];
    __shared__ int    s_idx[1024];
    __shared__ float4 s_bx[1024];
    __shared__ float  s_area[1024];
    __shared__ int    s_keep[1024];
    __shared__ int    s_cnt;

    int t = threadIdx.x;
    int c = blockIdx.x;

    if (t == 0) s_cnt = 0;
    __syncthreads();

    float th = g_thres;
    if (t < R_N) {
        float s = scores[t * NCLS_P1 + c];
        if (s > th) {
            int p = atomicAdd(&s_cnt, 1);
            s_score[p] = s;
            s_idx[p] = t;
        }
    }
    __syncthreads();
    int V = s_cnt;

    if (t >= V) {           // pad (never touched beyond sort region, but keep deterministic)
        s_score[t] = -INFINITY;
        s_idx[t]   = R_N + t;
    }
    __syncthreads();

    int P = 1;
    while (P < V) P <<= 1;

    // Bitonic "best-first" sort of [0, P): score desc, tie -> original index asc
    for (int k = 2; k <= P; k <<= 1) {
        for (int j = k >> 1; j > 0; j >>= 1) {
            if (t < P) {
                int ixj = t ^ j;
                if (ixj > t) {
                    float s1 = s_score[t], s2 = s_score[ixj];
                    int   i1 = s_idx[t],   i2 = s_idx[ixj];
                    bool before2 = (s2 > s1) || (s2 == s1 && i2 < i1); // elem at ixj should precede
                    bool dir = ((t & k) == 0);
                    if (before2 == dir) {
                        s_score[t] = s2; s_score[ixj] = s1;
                        s_idx[t]   = i2; s_idx[ixj]   = i1;
                    }
                }
            }
            __syncthreads();
        }
    }

    // Gather clipped boxes + areas for the V valid (now sorted) entries
    float4 mybox = make_float4(0.f, 0.f, 0.f, 0.f);
    float  myarea = 0.f;
    if (t < V) {
        int orig = s_idx[t];
        float4 b = __ldg((const float4*)boxes + orig * K_N + c);
        float x1 = fminf(fmaxf(b.x, 0.f), IMG_W_F);
        float y1 = fminf(fmaxf(b.y, 0.f), IMG_H_F);
        float x2 = fminf(fmaxf(b.z, 0.f), IMG_W_F);
        float y2 = fminf(fmaxf(b.w, 0.f), IMG_H_F);
        mybox = make_float4(x1, y1, x2, y2);
        myarea = fmaxf(x2 - x1, 0.f) * fmaxf(y2 - y1, 0.f);
        s_bx[t] = mybox;
        s_area[t] = myarea;
        s_keep[t] = 1;
    } else {
        s_keep[t] = 0;
    }
    __syncthreads();

    // Greedy NMS: iteration i suppresses j > i with IoU > 0.5 if keep[i]
    for (int i = 0; i < V; i++) {
        if (s_keep[i] && t > i && t < V) {
            float4 bi = s_bx[i];
            float xx1 = fmaxf(bi.x, mybox.x);
            float yy1 = fmaxf(bi.y, mybox.y);
            float xx2 = fminf(bi.z, mybox.z);
            float yy2 = fminf(bi.w, mybox.w);
            float inter = fmaxf(xx2 - xx1, 0.f) * fmaxf(yy2 - yy1, 0.f);
            float uni = fmaxf(s_area[i] + myarea - inter, 1e-9f);
            if (inter / uni > 0.5f) s_keep[t] = 0;
        }
        __syncthreads();
    }

    // Emit first (= best) 100 kept entries, pad rest with 0
    if (t == 0) {
        int base = c * CPC;
        int cnt = 0;
        for (int i = 0; i < V && cnt < CPC; i++) {
            if (s_keep[i]) {
                g_ord[base + cnt]  = ord32(s_score[i]);
                g_prop[base + cnt] = s_idx[i];
                cnt++;
            }
        }
        for (; cnt < CPC; cnt++) {
            g_ord[base + cnt] = 0u;
            g_prop[base + cnt] = 0;
        }
    }
}

// ---------------------------------------------------------------------------
// Kernel 3: exact 80-way merge (global top-100) + output assembly
// ---------------------------------------------------------------------------
__global__ void __launch_bounds__(1024) topk_kernel(const float* __restrict__ boxes,
                                                    const float* __restrict__ scores,
                                                    float* __restrict__ out) {
    __shared__ unsigned int sh_ord[K_N * CPC];
    __shared__ unsigned long long win[TOPK_N];
    int t = threadIdx.x;

    for (int i = t; i < K_N * CPC; i += 1024) sh_ord[i] = g_ord[i];
    __syncthreads();

    if (t < 32) {
        int lane = t;
        int c0 = lane, c1 = lane + 32, c2 = lane + 64;
        bool has2 = (c2 < K_N);
        int h0 = 0, h1 = 0, h2 = 0;
        // key = ord<<32 | c<<7 | k   (k < 100 fits 7 bits, c < 80 fits 7 bits)
        unsigned long long k0 = ((unsigned long long)sh_ord[c0 * CPC] << 32) | (unsigned)(c0 << 7);
        unsigned long long k1 = ((unsigned long long)sh_ord[c1 * CPC] << 32) | (unsigned)(c1 << 7);
        unsigned long long k2 = has2 ? (((unsigned long long)sh_ord[c2 * CPC] << 32) | (unsigned)(c2 << 7)) : 0ull;

        for (int r = 0; r < TOPK_N; r++) {
            unsigned long long b = umax64(k0, umax64(k1, k2));
            #pragma unroll
            for (int off = 16; off; off >>= 1)
                b = umax64(b, __shfl_xor_sync(0xffffffffu, b, off));
            if (lane == 0) win[r] = b;
            int wc = (int)((b >> 7) & 127u);
            if (wc == c0) {
                h0++;
                k0 = (h0 < CPC) ? (((unsigned long long)sh_ord[c0 * CPC + h0] << 32) | (unsigned)((c0 << 7) | h0)) : 0ull;
            } else if (wc == c1) {
                h1++;
                k1 = (h1 < CPC) ? (((unsigned long long)sh_ord[c1 * CPC + h1] << 32) | (unsigned)((c1 << 7) | h1)) : 0ull;
            } else if (has2 && wc == c2) {
                h2++;
                k2 = (h2 < CPC) ? (((unsigned long long)sh_ord[c2 * CPC + h2] << 32) | (unsigned)((c2 << 7) | h2)) : 0ull;
            }
        }
    }
    __syncthreads();

    // Output: [100, 87] = box(4) | score(1) | class(1) | full_scores(81)
    for (int e = t; e < TOPK_N * OUT_COLS; e += 1024) {
        int row = e / OUT_COLS;
        int col = e - row * OUT_COLS;
        unsigned long long key = win[row];
        unsigned int o = (unsigned int)(key >> 32);
        float val = 0.f;
        if (o != 0u) {
            int c = (int)((key >> 7) & 127u);
            int k = (int)(key & 127u);
            int prop = g_prop[c * CPC + k];
            if (col < 4) {
                float b = boxes[prop * (K_N * 4) + c * 4 + col];
                float lim = (col & 1) ? IMG_H_F : IMG_W_F;
                val = fminf(fmaxf(b, 0.f), lim);
            } else if (col == 4) {
                val = __uint_as_float(o & 0x7FFFFFFFu);
            } else if (col == 5) {
                val = (float)c;
            } else {
                val = scores[prop * NCLS_P1 + (col - 6)];
            }
        }
        out[e] = val;
    }
}

// ---------------------------------------------------------------------------
extern "C" void kernel_launch(void* const* d_in, const int* in_sizes, int n_in,
                              void* d_out, int out_size) {
    const float* boxes  = (const float*)d_in[0];
    const float* scores = (const float*)d_in[1];
    if (in_sizes[0] != R_N * K_N * 4) {  // defensive: identify by element count
        boxes  = (const float*)d_in[1];
        scores = (const float*)d_in[0];
    }
    thres_kernel<<<1, 1024>>>(scores);
    nms_kernel<<<K_N, 1024>>>(boxes, scores);
    topk_kernel<<<1, 1024>>>(boxes, scores, (float*)d_out);
}

// round 3
// speedup vs baseline: 1.3793x; 1.3793x over previous
#include <cuda_runtime.h>
#include <math.h>
#include <stdint.h>

#define R_N 1000
#define K_N 80
#define NCLS_P1 81
#define IMG_W_F 1333.0f
#define IMG_H_F 800.0f
#define CPC 100
#define TOPK_N 100
#define OUT_COLS 87
#define CAP 1024            // per-class candidate capacity (V <= 1000)
#define TB_NMS 128
#define NBLK_RED 64

typedef unsigned long long u64;

__device__ float g_psum[NBLK_RED];
__device__ float g_pmax[NBLK_RED];
__device__ unsigned int g_ord[K_N * CPC];   // per-class sorted kept scores (orderable), 0 = pad
__device__ int g_prop[K_N * CPC];           // original proposal row

__device__ __forceinline__ unsigned int ord32(float f) {
    unsigned int u = __float_as_uint(f);
    return (u & 0x80000000u) ? ~u : (u | 0x80000000u);
}

// ---------------------------------------------------------------------------
// Kernel 1: partial mean/max reduce over fg scores (64 blocks)
// ---------------------------------------------------------------------------
__global__ void __launch_bounds__(256) thres_partial(const float* __restrict__ scores) {
    __shared__ float s_sum[8];
    __shared__ float s_max[8];
    int t = threadIdx.x;
    float sum = 0.f, mx = -INFINITY;
    for (int idx = blockIdx.x * 256 + t; idx < R_N * K_N; idx += NBLK_RED * 256) {
        int r = idx / K_N;
        int c = idx - r * K_N;
        float v = __ldg(scores + r * NCLS_P1 + c);
        sum += v;
        mx = fmaxf(mx, v);
    }
    #pragma unroll
    for (int o = 16; o; o >>= 1) {
        sum += __shfl_xor_sync(0xffffffffu, sum, o);
        mx = fmaxf(mx, __shfl_xor_sync(0xffffffffu, mx, o));
    }
    if ((t & 31) == 0) { s_sum[t >> 5] = sum; s_max[t >> 5] = mx; }
    __syncthreads();
    if (t == 0) {
        float ts = 0.f, tm = -INFINITY;
        #pragma unroll
        for (int i = 0; i < 8; i++) { ts += s_sum[i]; tm = fmaxf(tm, s_max[i]); }
        g_psum[blockIdx.x] = ts;
        g_pmax[blockIdx.x] = tm;
    }
}

// ---------------------------------------------------------------------------
// Kernel 2: per-class compact -> bitonic sort -> greedy NMS -> emit top-100
// 128 threads per block; strided loops keep correctness for any V <= 1024.
// ---------------------------------------------------------------------------
__global__ void __launch_bounds__(TB_NMS) nms_kernel(const float* __restrict__ boxes,
                                                     const float* __restrict__ scores) {
    __shared__ float  s_score[CAP];
    __shared__ int    s_idx[CAP];
    __shared__ float4 s_bx[CAP];
    __shared__ float  s_area[CAP];
    __shared__ int    s_keep[CAP];
    __shared__ float  rs[NBLK_RED], rm[NBLK_RED];
    __shared__ int    s_cnt;

    int t = threadIdx.x;
    int c = blockIdx.x;

    // fold threshold partials
    if (t < NBLK_RED) { rs[t] = g_psum[t]; rm[t] = g_pmax[t]; }
    if (t == 0) s_cnt = 0;
    __syncthreads();
    #pragma unroll
    for (int s = NBLK_RED / 2; s > 0; s >>= 1) {
        if (t < s) { rs[t] += rs[t + s]; rm[t] = fmaxf(rm[t], rm[t + s]); }
        __syncthreads();
    }
    float th = fminf(0.05f, 0.5f * (rs[0] / (float)(R_N * K_N) + rm[0]));

    // compact valid entries (order scrambled by atomics; fixed by the sort below)
    for (int r = t; r < R_N; r += TB_NMS) {
        float s = __ldg(scores + r * NCLS_P1 + c);
        if (s > th) {
            int p = atomicAdd(&s_cnt, 1);
            s_score[p] = s;
            s_idx[p] = r;
        }
    }
    __syncthreads();
    int V = s_cnt;

    int P = 1;
    while (P < V) P <<= 1;

    for (int i = V + t; i < P; i += TB_NMS) {
        s_score[i] = -INFINITY;
        s_idx[i]   = R_N + i;
    }
    __syncthreads();

    // bitonic sort [0,P): score desc, tie -> index asc (total order, unique idx)
    for (int k = 2; k <= P; k <<= 1) {
        for (int j = k >> 1; j > 0; j >>= 1) {
            for (int i = t; i < P; i += TB_NMS) {
                int ixj = i ^ j;
                if (ixj > i) {
                    float s1 = s_score[i], s2 = s_score[ixj];
                    int   i1 = s_idx[i],   i2 = s_idx[ixj];
                    bool before2 = (s2 > s1) || (s2 == s1 && i2 < i1);
                    if (before2 == ((i & k) == 0)) {
                        s_score[i] = s2; s_score[ixj] = s1;
                        s_idx[i]   = i2; s_idx[ixj]   = i1;
                    }
                }
            }
            __syncthreads();
        }
    }

    // gather clipped boxes + areas
    for (int i = t; i < V; i += TB_NMS) {
        float4 b = __ldg((const float4*)boxes + s_idx[i] * K_N + c);
        float x1 = fminf(fmaxf(b.x, 0.f), IMG_W_F);
        float y1 = fminf(fmaxf(b.y, 0.f), IMG_H_F);
        float x2 = fminf(fmaxf(b.z, 0.f), IMG_W_F);
        float y2 = fminf(fmaxf(b.w, 0.f), IMG_H_F);
        s_bx[i] = make_float4(x1, y1, x2, y2);
        s_area[i] = fmaxf(x2 - x1, 0.f) * fmaxf(y2 - y1, 0.f);
        s_keep[i] = 1;
    }
    __syncthreads();

    // greedy NMS
    for (int i = 0; i < V; i++) {
        if (s_keep[i]) {
            float4 bi = s_bx[i];
            float  ai = s_area[i];
            for (int j = i + 1 + t; j < V; j += TB_NMS) {
                if (s_keep[j]) {
                    float4 bj = s_bx[j];
                    float xx1 = fmaxf(bi.x, bj.x);
                    float yy1 = fmaxf(bi.y, bj.y);
                    float xx2 = fminf(bi.z, bj.z);
                    float yy2 = fminf(bi.w, bj.w);
                    float inter = fmaxf(xx2 - xx1, 0.f) * fmaxf(yy2 - yy1, 0.f);
                    float uni = fmaxf(ai + s_area[j] - inter, 1e-9f);
                    if (inter > 0.5f * uni) s_keep[j] = 0;
                }
            }
        }
        __syncthreads();
    }

    // emit best 100 kept (already sorted), pad with 0
    if (t == 0) {
        int base = c * CPC;
        int cnt = 0;
        for (int i = 0; i < V && cnt < CPC; i++) {
            if (s_keep[i]) {
                g_ord[base + cnt]  = ord32(s_score[i]);
                g_prop[base + cnt] = s_idx[i];
                cnt++;
            }
        }
        for (; cnt < CPC; cnt++) {
            g_ord[base + cnt] = 0u;
            g_prop[base + cnt] = 0;
        }
    }
}

// ---------------------------------------------------------------------------
// Kernel 3: parallel tournament merge of 80 sorted lists -> top-100 + output
// ---------------------------------------------------------------------------
__device__ __forceinline__ void merge_lists(const u64* __restrict__ src,
                                            u64* __restrict__ dst, int n, int t) {
    int npair = n >> 1;
    int total = npair * 200;
    for (int w = t; w < total; w += 1024) {
        int p = w / 200, e = w - p * 200;
        const u64* X = src + (2 * p) * CPC;
        const u64* Y = X + CPC;
        u64 v; int base; const u64* other;
        if (e < CPC) { v = X[e];       base = e;       other = Y; }
        else         { v = Y[e - CPC]; base = e - CPC; other = X; }
        int lo = 0, hi = CPC;                       // count(other > v), keys unique
        while (lo < hi) { int mid = (lo + hi) >> 1; if (other[mid] > v) lo = mid + 1; else hi = mid; }
        int pos = base + lo;
        if (pos < CPC) dst[p * CPC + pos] = v;
    }
    if (n & 1)
        for (int w = t; w < CPC; w += 1024) dst[npair * CPC + w] = src[(n - 1) * CPC + w];
}

__global__ void __launch_bounds__(1024) topk_kernel(const float* __restrict__ boxes,
                                                    const float* __restrict__ scores,
                                                    float* __restrict__ out) {
    extern __shared__ u64 sm[];
    u64* K = sm;                    // 80 lists (8000)
    u64* A = K + K_N * CPC;         // up to 40 lists (4000)
    u64* B = A + 40 * CPC;          // up to 20 lists (2000)
    int t = threadIdx.x;

    // key = ord<<32 | (79-c)<<7 | (99-k): ties break like flat top_k (smaller c, then k)
    for (int i = t; i < K_N * CPC; i += 1024) {
        int c = i / CPC, k = i - c * CPC;
        K[i] = ((u64)g_ord[i] << 32) | (unsigned)(((K_N - 1 - c) << 7) | (CPC - 1 - k));
    }
    __syncthreads();

    merge_lists(K, A, 80, t); __syncthreads();   // 80 -> 40
    merge_lists(A, B, 40, t); __syncthreads();   // 40 -> 20
    merge_lists(B, A, 20, t); __syncthreads();   // 20 -> 10
    merge_lists(A, B, 10, t); __syncthreads();   // 10 -> 5
    merge_lists(B, A, 5, t);  __syncthreads();   // 5  -> 3
    merge_lists(A, B, 3, t);  __syncthreads();   // 3  -> 2
    merge_lists(B, A, 2, t);  __syncthreads();   // 2  -> 1 (result in A[0..99])

    // Output: [100, 87] = box(4) | score | class | full_scores(81)
    for (int e = t; e < TOPK_N * OUT_COLS; e += 1024) {
        int row = e / OUT_COLS;
        int col = e - row * OUT_COLS;
        u64 key = A[row];
        unsigned int o = (unsigned int)(key >> 32);
        float val = 0.f;
        if (o != 0u) {
            int c = (K_N - 1) - (int)((key >> 7) & 127u);
            int k = (CPC - 1) - (int)(key & 127u);
            int prop = g_prop[c * CPC + k];
            if (col < 4) {
                float b = __ldg(boxes + prop * (K_N * 4) + c * 4 + col);
                float lim = (col & 1) ? IMG_H_F : IMG_W_F;
                val = fminf(fmaxf(b, 0.f), lim);
            } else if (col == 4) {
                val = __uint_as_float(o & 0x7FFFFFFFu);
            } else if (col == 5) {
                val = (float)c;
            } else {
                val = __ldg(scores + prop * NCLS_P1 + (col - 6));
            }
        }
        out[e] = val;
    }
}

// ---------------------------------------------------------------------------
extern "C" void kernel_launch(void* const* d_in, const int* in_sizes, int n_in,
                              void* d_out, int out_size) {
    const float* boxes  = (const float*)d_in[0];
    const float* scores = (const float*)d_in[1];
    if (in_sizes[0] != R_N * K_N * 4) {
        boxes  = (const float*)d_in[1];
        scores = (const float*)d_in[0];
    }
    static const size_t TOPK_SMEM = (size_t)(K_N * CPC + 40 * CPC + 20 * CPC) * sizeof(u64); // 112 KB
    cudaFuncSetAttribute(topk_kernel, cudaFuncAttributeMaxDynamicSharedMemorySize, (int)TOPK_SMEM);
    thres_partial<<<NBLK_RED, 256>>>(scores);
    nms_kernel<<<K_N, TB_NMS>>>(boxes, scores);
    topk_kernel<<<1, 1024, TOPK_SMEM>>>(boxes, scores, (float*)d_out);
}